// round 13
// baseline (speedup 1.0000x reference)
#include <cuda_runtime.h>

// Depthwise Conv1d: B=32, C=128, L=8192, kernel=3, stride=1, pad=1, fp32.
// out[b,c,l] = w[c,0]*x[b,c,l-1] + w[c,1]*x[b,c,l] + w[c,2]*x[b,c,l+1] + bias[c]
//
// R13 = R4 (best measured: 36.6us kernel, DRAM 74.6%) + streaming stores.
// Output is write-once/never-read: __stcs (evict-first) keeps those lines
// from displacing the input stream in L2. Loads stay default-cached (halo
// scalar loads rely on L1/L2 hits of the vector-load lines).
// Structure is otherwise byte-identical to R4: grid-strided ILP=4,
// per-instruction coalesced LDG.128/STG.128, per-iteration taps (regs=32,
// occ ~84% — the measured sweet spot).

#define BATCH 32
#define CHANS 128
#define LEN   8192
#define LEN4  (LEN / 4)          // 2048 float4 per row
#define ROWS  (BATCH * CHANS)    // 4096
#define NTHREADS 256
#define ITER 4
#define TOTAL4   (ROWS * LEN4)               // 8,388,608 float4
#define NTHREADS_TOTAL (TOTAL4 / ITER)       // 2,097,152
#define NBLOCKS  (NTHREADS_TOTAL / NTHREADS) // 8192

__global__ __launch_bounds__(NTHREADS)
void dwconv1d_kernel(const float* __restrict__ x,
                     const float* __restrict__ w,
                     const float* __restrict__ bias,
                     float* __restrict__ out)
{
    const unsigned int gid    = blockIdx.x * NTHREADS + threadIdx.x;
    const unsigned int stride = NTHREADS_TOTAL; // uniform grid stride

    unsigned int idx[ITER], row[ITER], j[ITER], c[ITER];
#pragma unroll
    for (int i = 0; i < ITER; i++) {
        idx[i] = gid + i * stride;
        row[i] = idx[i] >> 11;         // / LEN4
        j[i]   = idx[i] & (LEN4 - 1);  // within-row float4 index
        c[i]   = row[i] & (CHANS - 1);
    }

    // ---- front-batched vector loads (high MLP, fully coalesced) ----
    float4 v[ITER];
#pragma unroll
    for (int i = 0; i < ITER; i++)
        v[i] = reinterpret_cast<const float4*>(x)[idx[i]];

    // ---- halo loads (L1 hits: same/adjacent lines as neighbors' vec loads) ----
    float left[ITER], right[ITER];
#pragma unroll
    for (int i = 0; i < ITER; i++) {
        const float* xs = x + (size_t)row[i] * LEN;
        unsigned int e0 = 4u * j[i];
        left[i]  = (j[i] == 0)        ? 0.0f : __ldg(&xs[e0 - 1]);
        right[i] = (j[i] == LEN4 - 1) ? 0.0f : __ldg(&xs[e0 + 4]);
    }

    // ---- per-channel taps (uniform within warp -> L1 broadcast) ----
    float w0[ITER], w1[ITER], w2[ITER], bb[ITER];
#pragma unroll
    for (int i = 0; i < ITER; i++) {
        w0[i] = __ldg(&w[c[i] * 3 + 0]);
        w1[i] = __ldg(&w[c[i] * 3 + 1]);
        w2[i] = __ldg(&w[c[i] * 3 + 2]);
        bb[i] = __ldg(&bias[c[i]]);
    }

    // ---- compute + streaming (evict-first) stores ----
#pragma unroll
    for (int i = 0; i < ITER; i++) {
        float4 o;
        o.x = fmaf(w0[i], left[i], fmaf(w1[i], v[i].x, fmaf(w2[i], v[i].y, bb[i])));
        o.y = fmaf(w0[i], v[i].x,  fmaf(w1[i], v[i].y, fmaf(w2[i], v[i].z, bb[i])));
        o.z = fmaf(w0[i], v[i].y,  fmaf(w1[i], v[i].z, fmaf(w2[i], v[i].w, bb[i])));
        o.w = fmaf(w0[i], v[i].z,  fmaf(w1[i], v[i].w, fmaf(w2[i], right[i], bb[i])));
        __stcs(&reinterpret_cast<float4*>(out)[idx[i]], o);
    }
}

extern "C" void kernel_launch(void* const* d_in, const int* in_sizes, int n_in,
                              void* d_out, int out_size)
{
    const float* x    = (const float*)d_in[0];
    const float* w    = (const float*)d_in[1];
    const float* bias = (const float*)d_in[2];
    float* out        = (float*)d_out;

    dwconv1d_kernel<<<NBLOCKS, NTHREADS>>>(x, w, bias, out);
}

// round 14
// speedup vs baseline: 1.1103x; 1.1103x over previous
#include <cuda_runtime.h>

// Depthwise Conv1d: B=32, C=128, L=8192, kernel=3, stride=1, pad=1, fp32.
// out[b,c,l] = w[c,0]*x[b,c,l-1] + w[c,1]*x[b,c,l] + w[c,2]*x[b,c,l+1] + bias[c]
//
// FINAL (= R4, best of 10 measured variants: 36.6us kernel, DRAM 74.6%,
// dur 43.5us). Grid-strided ILP=4: each thread handles 4 float4s spaced
// gridDim*blockDim apart, so every load/store instruction is perfectly
// coalesced while per-thread MLP is 4 front-batched LDG.128. Halo elements
// are scalar loads that hit L1 (same/adjacent lines as neighbors' vector
// loads). Default cache ops throughout — measured faster than __ldcs/__stcs
// on sm_103a. regs=32 / occ ~84% is the measured sweet spot; every higher-
// ILP, shuffle, cp.async, persistent, or cache-hint variant benched slower.

#define BATCH 32
#define CHANS 128
#define LEN   8192
#define LEN4  (LEN / 4)          // 2048 float4 per row
#define ROWS  (BATCH * CHANS)    // 4096
#define NTHREADS 256
#define ITER 4
#define TOTAL4   (ROWS * LEN4)               // 8,388,608 float4
#define NTHREADS_TOTAL (TOTAL4 / ITER)       // 2,097,152
#define NBLOCKS  (NTHREADS_TOTAL / NTHREADS) // 8192

__global__ __launch_bounds__(NTHREADS)
void dwconv1d_kernel(const float* __restrict__ x,
                     const float* __restrict__ w,
                     const float* __restrict__ bias,
                     float* __restrict__ out)
{
    const unsigned int gid    = blockIdx.x * NTHREADS + threadIdx.x;
    const unsigned int stride = NTHREADS_TOTAL; // uniform grid stride

    unsigned int idx[ITER], row[ITER], j[ITER], c[ITER];
#pragma unroll
    for (int i = 0; i < ITER; i++) {
        idx[i] = gid + i * stride;
        row[i] = idx[i] >> 11;         // / LEN4
        j[i]   = idx[i] & (LEN4 - 1);  // within-row float4 index
        c[i]   = row[i] & (CHANS - 1);
    }

    // ---- front-batched vector loads (high MLP, fully coalesced) ----
    float4 v[ITER];
#pragma unroll
    for (int i = 0; i < ITER; i++)
        v[i] = reinterpret_cast<const float4*>(x)[idx[i]];

    // ---- halo loads (L1 hits: same/adjacent lines as neighbors' vec loads) ----
    float left[ITER], right[ITER];
#pragma unroll
    for (int i = 0; i < ITER; i++) {
        const float* xs = x + (size_t)row[i] * LEN;
        unsigned int e0 = 4u * j[i];
        left[i]  = (j[i] == 0)        ? 0.0f : __ldg(&xs[e0 - 1]);
        right[i] = (j[i] == LEN4 - 1) ? 0.0f : __ldg(&xs[e0 + 4]);
    }

    // ---- per-channel taps (uniform within warp -> L1 broadcast) ----
    float w0[ITER], w1[ITER], w2[ITER], bb[ITER];
#pragma unroll
    for (int i = 0; i < ITER; i++) {
        w0[i] = __ldg(&w[c[i] * 3 + 0]);
        w1[i] = __ldg(&w[c[i] * 3 + 1]);
        w2[i] = __ldg(&w[c[i] * 3 + 2]);
        bb[i] = __ldg(&bias[c[i]]);
    }

    // ---- compute + store ----
#pragma unroll
    for (int i = 0; i < ITER; i++) {
        float4 o;
        o.x = fmaf(w0[i], left[i], fmaf(w1[i], v[i].x, fmaf(w2[i], v[i].y, bb[i])));
        o.y = fmaf(w0[i], v[i].x,  fmaf(w1[i], v[i].y, fmaf(w2[i], v[i].z, bb[i])));
        o.z = fmaf(w0[i], v[i].y,  fmaf(w1[i], v[i].z, fmaf(w2[i], v[i].w, bb[i])));
        o.w = fmaf(w0[i], v[i].z,  fmaf(w1[i], v[i].w, fmaf(w2[i], right[i], bb[i])));
        reinterpret_cast<float4*>(out)[idx[i]] = o;
    }
}

extern "C" void kernel_launch(void* const* d_in, const int* in_sizes, int n_in,
                              void* d_out, int out_size)
{
    const float* x    = (const float*)d_in[0];
    const float* w    = (const float*)d_in[1];
    const float* bias = (const float*)d_in[2];
    float* out        = (float*)d_out;

    dwconv1d_kernel<<<NBLOCKS, NTHREADS>>>(x, w, bias, out);
}